// round 15
// baseline (speedup 1.0000x reference)
#include <cuda_runtime.h>
#include <cuda_fp16.h>

#define NN 50000
#define NE 1600000
#define NG 64
#define FN 32
#define FE 16
#define HD 64
#define NL 3
#define BN_EPS 1e-5f
#define SCAN_B 1024
#define SCAN_NB ((NN + SCAN_B - 1) / SCAN_B)   // 49

typedef unsigned long long ull;

// ---------------- static device scratch (no allocs allowed) ----------------
__device__ float  g_h[(size_t)NN * HD];         // embed output (layer-0 input)
__device__ float  g_za[(size_t)NN * HD];        // z2 ping
__device__ float  g_zb[(size_t)NN * HD];        // z2 pong
__device__ float  g_zt[(size_t)NN * HD];        // agg output z
__device__ __half g_e[(size_t)NE * HD];         // edge embeddings (fp16), CSR order
__device__ int    g_src[NE];                    // src node per CSR slot
__device__ int    g_pos[NE];                    // edge id -> CSR slot
__device__ int    g_rowptr[NN + 1];
__device__ int    g_cnt[NN];                    // histogram, then cursor
__device__ int    g_bsum[SCAN_NB];
__device__ int    g_boff[SCAN_NB];
__device__ float  g_part[128];                  // BN sum/sumsq accumulators
__device__ float  g_mu[HD], g_inv[HD];
__device__ int    g_is64;                       // index dtype flag

// ---- f32x2 packed helpers (Blackwell FFMA2) ----
__device__ __forceinline__ ull pack2(float lo, float hi) {
    ull r;
    asm("mov.b64 %0, {%1, %2};" : "=l"(r) : "f"(lo), "f"(hi));
    return r;
}
__device__ __forceinline__ void unpack2(ull v, float& lo, float& hi) {
    asm("mov.b64 {%0, %1}, %2;" : "=f"(lo), "=f"(hi) : "l"(v));
}
__device__ __forceinline__ void fma2(ull& d, ull a, ull b) {
    asm("fma.rn.f32x2 %0, %1, %2, %0;" : "+l"(d) : "l"(a), "l"(b));
}

__device__ __forceinline__ int load_idx(const void* p, long long i, int is64) {
    if (is64) return (int)((const long long*)p)[i];
    return ((const int*)p)[i];
}

__device__ __forceinline__ const float* buf_sel(int s) {
    return (s == 0) ? g_h : (s == 1) ? g_za : g_zb;
}
__device__ __forceinline__ float* buf_sel_w(int s) {
    return (s == 1) ? g_za : g_zb;
}

// Detect whether ei is int64 (all odd int32 slots == 0) or int32.
__global__ void probe_k(const int* __restrict__ ei32) {
    if (threadIdx.x != 0 || blockIdx.x != 0) return;
    int all0 = 1;
    for (int k = 0; k < 256; k++) {
        long long slot = 1 + 2LL * ((long long)k * 6247);
        if (slot < 2LL * NE && ei32[slot] != 0) { all0 = 0; break; }
    }
    g_is64 = all0;
}

__global__ void zero_cnt_k() {
    int i = blockIdx.x * blockDim.x + threadIdx.x;
    if (i < NN) g_cnt[i] = 0;
}

// h = x @ node_W + node_b   (warp per row, lane owns 2 cols)
__global__ void node_embed_k(const float* __restrict__ x,
                             const float* __restrict__ W,
                             const float* __restrict__ b) {
    int r = (blockIdx.x * blockDim.x + threadIdx.x) >> 5;
    int lane = threadIdx.x & 31;
    if (r >= NN) return;
    float2 acc = make_float2(b[2 * lane], b[2 * lane + 1]);
    const float* xr = x + (size_t)r * FN;
#pragma unroll
    for (int k = 0; k < FN; k++) {
        float xv = __ldg(xr + k);
        float2 wv = *(const float2*)(W + k * HD + 2 * lane);
        acc.x += xv * wv.x;
        acc.y += xv * wv.y;
    }
    *(float2*)(g_h + (size_t)r * HD + 2 * lane) = acc;
}

__global__ void hist_k(const void* __restrict__ ei) {
    int is64 = g_is64;
    for (long long i = blockIdx.x * blockDim.x + threadIdx.x; i < NE;
         i += (long long)gridDim.x * blockDim.x)
        atomicAdd(&g_cnt[load_idx(ei, NE + i, is64)], 1);
}

// ---- 3-kernel coalesced exclusive scan of g_cnt -> g_rowptr (+cursor) ----
__global__ void scan_partial_k() {
    int i = blockIdx.x * SCAN_B + threadIdx.x;
    int v = (i < NN) ? g_cnt[i] : 0;
    int lane = threadIdx.x & 31, w = threadIdx.x >> 5;
#pragma unroll
    for (int off = 16; off; off >>= 1) v += __shfl_down_sync(0xffffffffu, v, off);
    __shared__ int ws[32];
    if (lane == 0) ws[w] = v;
    __syncthreads();
    if (w == 0) {
        int t = ws[lane];
#pragma unroll
        for (int off = 16; off; off >>= 1) t += __shfl_down_sync(0xffffffffu, t, off);
        if (lane == 0) g_bsum[blockIdx.x] = t;
    }
}

__global__ void scan_tops_k() {
    if (threadIdx.x != 0) return;
    int run = 0;
    for (int b = 0; b < SCAN_NB; b++) {
        g_boff[b] = run;
        run += g_bsum[b];
    }
    g_rowptr[NN] = run;
}

__global__ void scan_final_k() {
    int i = blockIdx.x * SCAN_B + threadIdx.x;
    int v = (i < NN) ? g_cnt[i] : 0;
    int lane = threadIdx.x & 31, w = threadIdx.x >> 5;
    int inc = v;
#pragma unroll
    for (int off = 1; off < 32; off <<= 1) {
        int n = __shfl_up_sync(0xffffffffu, inc, off);
        if (lane >= off) inc += n;
    }
    __shared__ int ws[32];
    if (lane == 31) ws[w] = inc;
    __syncthreads();
    if (w == 0) {
        int t = ws[lane];
        int e = t;
#pragma unroll
        for (int off = 1; off < 32; off <<= 1) {
            int n = __shfl_up_sync(0xffffffffu, e, off);
            if (lane >= off) e += n;
        }
        ws[lane] = e - t;  // exclusive warp offset
    }
    __syncthreads();
    int excl = g_boff[blockIdx.x] + ws[w] + inc - v;
    if (i < NN) { g_rowptr[i] = excl; g_cnt[i] = excl; }
}

// thread per edge: assign CSR slot, record src (scattered) + pos (coalesced)
__global__ void pos_k(const void* __restrict__ ei) {
    long long i = (long long)blockIdx.x * blockDim.x + threadIdx.x;
    if (i >= NE) return;
    int is64 = g_is64;
    int dst = load_idx(ei, NE + i, is64);
    int p = atomicAdd(&g_cnt[dst], 1);
    g_src[p] = load_idx(ei, i, is64);
    g_pos[(int)i] = p;
}

// e = edge_attr @ edge_W + edge_b (fp16), written to CSR slot (plain stores).
// Tiled GEMM: 256 edges/block, thread = 8 edges x 8 cols, f32x2 FMA.
__global__ __launch_bounds__(256) void edge_gemm_k(const float* __restrict__ ea,
                                                   const float* __restrict__ W,
                                                   const float* __restrict__ b) {
    __shared__ __align__(16) float sea[256 * 17];
    __shared__ __align__(16) float sW[16 * 64];
    __shared__ __align__(16) float sb[64];
    int tid = threadIdx.x;
    long long e0 = (long long)blockIdx.x * 256;
    const float4* gea = (const float4*)(ea + e0 * FE);
    for (int i = tid; i < 1024; i += 256) {
        float4 v = gea[i];
        int e = i >> 2, k4 = (i & 3) << 2;
        float* d = &sea[e * 17 + k4];
        d[0] = v.x; d[1] = v.y; d[2] = v.z; d[3] = v.w;
    }
    for (int i = tid; i < 1024; i += 256) sW[i] = W[i];
    if (tid < 64) sb[tid] = b[tid];
    __syncthreads();

    int cg = tid & 7, eg = tid >> 3;     // 8 col-groups x 32 edge-groups
    ull acc[8][4];
#pragma unroll
    for (int p = 0; p < 4; p++) {
        ull bv = *(const ull*)&sb[cg * 8 + 2 * p];
#pragma unroll
        for (int j = 0; j < 8; j++) acc[j][p] = bv;
    }
#pragma unroll
    for (int k = 0; k < FE; k++) {
        ull w0 = *(const ull*)&sW[k * 64 + cg * 8];
        ull w1 = *(const ull*)&sW[k * 64 + cg * 8 + 2];
        ull w2 = *(const ull*)&sW[k * 64 + cg * 8 + 4];
        ull w3 = *(const ull*)&sW[k * 64 + cg * 8 + 6];
#pragma unroll
        for (int j = 0; j < 8; j++) {
            float a = sea[(eg * 8 + j) * 17 + k];
            ull a2 = pack2(a, a);
            fma2(acc[j][0], a2, w0);
            fma2(acc[j][1], a2, w1);
            fma2(acc[j][2], a2, w2);
            fma2(acc[j][3], a2, w3);
        }
    }
#pragma unroll
    for (int j = 0; j < 8; j++) {
        long long e = e0 + eg * 8 + j;
        int p = __ldg(&g_pos[(int)e]);
        uint4 o;
        float lo, hi;
        __half2 hh;
        unpack2(acc[j][0], lo, hi); hh = __floats2half2_rn(lo, hi); o.x = *(unsigned*)&hh;
        unpack2(acc[j][1], lo, hi); hh = __floats2half2_rn(lo, hi); o.y = *(unsigned*)&hh;
        unpack2(acc[j][2], lo, hi); hh = __floats2half2_rn(lo, hi); o.z = *(unsigned*)&hh;
        unpack2(acc[j][3], lo, hi); hh = __floats2half2_rn(lo, hi); o.w = *(unsigned*)&hh;
        *(uint4*)(g_e + (size_t)p * HD + cg * 8) = o;
    }
}

// warp per dst node: z = h + sum_in relu(h[src] + e)  (BN fold of prev layer)
// e reads are fully sequential (CSR order), plain caching.
__global__ void agg_k(int srcsel, int use_bn,
                      const float* __restrict__ gamma,
                      const float* __restrict__ beta) {
    int v = (blockIdx.x * blockDim.x + threadIdx.x) >> 5;
    int lane = threadIdx.x & 31;
    if (v >= NN) return;
    const float* srcb = buf_sel(srcsel);

    float2 A = make_float2(1.f, 1.f), B = make_float2(0.f, 0.f);
    if (use_bn) {
        A.x = gamma[2 * lane] * g_inv[2 * lane];
        A.y = gamma[2 * lane + 1] * g_inv[2 * lane + 1];
        B.x = beta[2 * lane] - g_mu[2 * lane] * A.x;
        B.y = beta[2 * lane + 1] - g_mu[2 * lane + 1] * A.y;
    }

    int s0 = g_rowptr[v], s1 = g_rowptr[v + 1];
    float2 acc = make_float2(0.f, 0.f);
    const __half2* ep = (const __half2*)g_e;
    for (int s = s0; s < s1; s += 32) {
        int n = min(32, s1 - s);
        int mysrc = (lane < n) ? __ldg(&g_src[s + lane]) : 0;
        if (n == 32) {
#pragma unroll 8
            for (int j = 0; j < 32; j++) {
                int sc = __shfl_sync(0xffffffffu, mysrc, j);
                float2 ev = __half22float2(ep[(size_t)(s + j) * 32 + lane]);
                float2 hs = *(const float2*)(srcb + (size_t)sc * HD + 2 * lane);
                if (use_bn) {
                    hs.x = fmaxf(fmaf(A.x, hs.x, B.x), 0.f);
                    hs.y = fmaxf(fmaf(A.y, hs.y, B.y), 0.f);
                }
                acc.x += fmaxf(hs.x + ev.x, 0.f);
                acc.y += fmaxf(hs.y + ev.y, 0.f);
            }
        } else {
            for (int j = 0; j < n; j++) {
                int sc = __shfl_sync(0xffffffffu, mysrc, j);
                float2 ev = __half22float2(ep[(size_t)(s + j) * 32 + lane]);
                float2 hs = *(const float2*)(srcb + (size_t)sc * HD + 2 * lane);
                if (use_bn) {
                    hs.x = fmaxf(fmaf(A.x, hs.x, B.x), 0.f);
                    hs.y = fmaxf(fmaf(A.y, hs.y, B.y), 0.f);
                }
                acc.x += fmaxf(hs.x + ev.x, 0.f);
                acc.y += fmaxf(hs.y + ev.y, 0.f);
            }
        }
    }
    float2 hv = *(const float2*)(srcb + (size_t)v * HD + 2 * lane);
    if (use_bn) {
        hv.x = fmaxf(fmaf(A.x, hv.x, B.x), 0.f);
        hv.y = fmaxf(fmaf(A.y, hv.y, B.y), 0.f);
    }
    *(float2*)(g_zt + (size_t)v * HD + 2 * lane) =
        make_float2(hv.x + acc.x, hv.y + acc.y);
}

// GINE MLP as register-tiled GEMM pair + fused BN-stat accumulation.
#define SZ_OFF   0
#define SW_OFF   4352                 // 64*68
#define SH_OFF   (SW_OFF + 8192)      // + 64*128
#define SB1_OFF  (SH_OFF + 8448)      // + 64*132
#define SB2_OFF  (SB1_OFF + 128)
#define MLP_SMEM ((SB2_OFF + 64) * 4)
__global__ __launch_bounds__(256) void mlp_gemm_k(int dstsel,
                                                  const float* __restrict__ W1,
                                                  const float* __restrict__ b1,
                                                  const float* __restrict__ W2,
                                                  const float* __restrict__ b2) {
    extern __shared__ __align__(16) float sm[];
    float* sz = sm + SZ_OFF;    // [64][68]
    float* sW = sm + SW_OFF;    // [64][128] then [128][64]
    float* sh = sm + SH_OFF;    // [64][132]
    float* sb1 = sm + SB1_OFF;
    float* sb2 = sm + SB2_OFF;
    __shared__ float sstat[128];
    int tid = threadIdx.x;
    int r0 = blockIdx.x * 64;

    if (tid < 128) sstat[tid] = 0.f;
    for (int i = tid; i < 1024; i += 256) {
        int r = i >> 4, c4 = (i & 15) << 2;
        float4 v = make_float4(0.f, 0.f, 0.f, 0.f);
        if (r0 + r < NN) v = *(const float4*)&g_zt[(size_t)(r0 + r) * HD + c4];
        *(float4*)&sz[r * 68 + c4] = v;
    }
    for (int i = tid; i < 8192; i += 256) sW[i] = W1[i];
    if (tid < 128) sb1[tid] = b1[tid];
    else if (tid < 192) sb2[tid - 128] = b2[tid - 128];
    __syncthreads();

    // GEMM1: 64x128 = (rg:8 rows x 8) x (cg:32 cols x 4)
    {
        int cg = tid & 31, rg = tid >> 5;
        ull acc[8][2];
        ull bb0 = *(const ull*)&sb1[cg * 4];
        ull bb1 = *(const ull*)&sb1[cg * 4 + 2];
#pragma unroll
        for (int j = 0; j < 8; j++) { acc[j][0] = bb0; acc[j][1] = bb1; }
#pragma unroll 4
        for (int k = 0; k < 64; k++) {
            ull w0 = *(const ull*)&sW[k * 128 + cg * 4];
            ull w1 = *(const ull*)&sW[k * 128 + cg * 4 + 2];
#pragma unroll
            for (int j = 0; j < 8; j++) {
                float a = sz[(rg * 8 + j) * 68 + k];
                ull a2 = pack2(a, a);
                fma2(acc[j][0], a2, w0);
                fma2(acc[j][1], a2, w1);
            }
        }
#pragma unroll
        for (int j = 0; j < 8; j++) {
            float x0, x1, x2, x3;
            unpack2(acc[j][0], x0, x1);
            unpack2(acc[j][1], x2, x3);
            float4 hv = make_float4(fmaxf(x0, 0.f), fmaxf(x1, 0.f),
                                    fmaxf(x2, 0.f), fmaxf(x3, 0.f));
            *(float4*)&sh[(rg * 8 + j) * 132 + cg * 4] = hv;
        }
    }
    __syncthreads();
    for (int i = tid; i < 8192; i += 256) sW[i] = W2[i];
    __syncthreads();

    // GEMM2: 64x64 = (rg2:16 rows x 4) x (cg2:16 cols x 4)
    {
        int cg2 = tid & 15, rg2 = tid >> 4;
        ull acc[4][2];
        ull bb0 = *(const ull*)&sb2[cg2 * 4];
        ull bb1 = *(const ull*)&sb2[cg2 * 4 + 2];
#pragma unroll
        for (int j = 0; j < 4; j++) { acc[j][0] = bb0; acc[j][1] = bb1; }
#pragma unroll 4
        for (int k = 0; k < 128; k++) {
            ull w0 = *(const ull*)&sW[k * 64 + cg2 * 4];
            ull w1 = *(const ull*)&sW[k * 64 + cg2 * 4 + 2];
#pragma unroll
            for (int j = 0; j < 4; j++) {
                float a = sh[(rg2 * 4 + j) * 132 + k];
                ull a2 = pack2(a, a);
                fma2(acc[j][0], a2, w0);
                fma2(acc[j][1], a2, w1);
            }
        }
        float* dstb = buf_sel_w(dstsel);
        float cs[4] = {0.f, 0.f, 0.f, 0.f};
        float cq[4] = {0.f, 0.f, 0.f, 0.f};
#pragma unroll
        for (int j = 0; j < 4; j++) {
            int r = r0 + rg2 * 4 + j;
            if (r < NN) {
                float x0, x1, x2, x3;
                unpack2(acc[j][0], x0, x1);
                unpack2(acc[j][1], x2, x3);
                *(float4*)&dstb[(size_t)r * HD + cg2 * 4] =
                    make_float4(x0, x1, x2, x3);
                cs[0] += x0; cs[1] += x1; cs[2] += x2; cs[3] += x3;
                cq[0] += x0 * x0; cq[1] += x1 * x1;
                cq[2] += x2 * x2; cq[3] += x3 * x3;
            }
        }
#pragma unroll
        for (int p = 0; p < 4; p++) {
            atomicAdd(&sstat[cg2 * 4 + p], cs[p]);
            atomicAdd(&sstat[64 + cg2 * 4 + p], cq[p]);
        }
    }
    __syncthreads();
    if (tid < 128) atomicAdd(&g_part[tid], sstat[tid]);
}

// Read BN accumulators, compute mu/inv, RE-ZERO g_part for next use
// (keeps the captured graph deterministic across replays).
__global__ void bn_finalize_k() {
    int t = threadIdx.x;  // 64 threads
    float s = g_part[t];
    float s2 = g_part[64 + t];
    g_part[t] = 0.f;
    g_part[64 + t] = 0.f;
    float mu = s / (float)NN;
    float var = s2 / (float)NN - mu * mu;
    g_mu[t] = mu;
    g_inv[t] = rsqrtf(var + BN_EPS);
}

// batch sorted -> contiguous ranges; BN+relu on the fly, mean-pool, head.
__global__ void pool_final_k(int sel, const void* __restrict__ batch,
                             const float* __restrict__ gamma,
                             const float* __restrict__ beta,
                             const float* __restrict__ lw,
                             const float* __restrict__ lb,
                             float* __restrict__ out) {
    int g = blockIdx.x;
    int is64 = g_is64;
    const float* buf = buf_sel(sel);
    __shared__ int s_range[2];
    if (threadIdx.x == 0) {
        int lo = 0, hi = NN;
        while (lo < hi) { int mid = (lo + hi) >> 1; if (load_idx(batch, mid, is64) < g) lo = mid + 1; else hi = mid; }
        s_range[0] = lo;
        hi = NN;
        while (lo < hi) { int mid = (lo + hi) >> 1; if (load_idx(batch, mid, is64) < g + 1) lo = mid + 1; else hi = mid; }
        s_range[1] = lo;
    }
    __syncthreads();
    int start = s_range[0], end = s_range[1];
    int c = threadIdx.x & 63, rg = threadIdx.x >> 6;
    float a = gamma[c] * g_inv[c];
    float bb = beta[c] - g_mu[c] * a;
    float s = 0.f;
    for (int r = start + rg; r < end; r += 4)
        s += fmaxf(fmaf(a, buf[(size_t)r * HD + c], bb), 0.f);
    __shared__ float ps[256];
    ps[threadIdx.x] = s;
    __syncthreads();
    if (threadIdx.x < 128) ps[threadIdx.x] += ps[threadIdx.x + 128];
    __syncthreads();
    if (threadIdx.x < 64) {
        float gs = ps[threadIdx.x] + ps[threadIdx.x + 64];
        float cnt = fmaxf((float)(end - start), 1.0f);
        ps[threadIdx.x] = gs / cnt * lw[threadIdx.x];
    }
    __syncthreads();
    if (threadIdx.x < 32) {
        float t = ps[threadIdx.x] + ps[threadIdx.x + 32];
#pragma unroll
        for (int off = 16; off; off >>= 1) t += __shfl_down_sync(0xffffffffu, t, off);
        if (threadIdx.x == 0) out[g] = t + lb[0];
    }
}

// ---------------- launcher ----------------
extern "C" void kernel_launch(void* const* d_in, const int* in_sizes, int n_in,
                              void* d_out, int out_size) {
    const float* x = (const float*)d_in[0];
    const float* ea = (const float*)d_in[1];
    const void* ei = d_in[2];
    const void* batch = d_in[3];
    const float* node_W = (const float*)d_in[4];
    const float* node_b = (const float*)d_in[5];
    const float* edge_W = (const float*)d_in[6];
    const float* edge_b = (const float*)d_in[7];
    const float* W1s = (const float*)d_in[8];
    const float* b1s = (const float*)d_in[9];
    const float* W2s = (const float*)d_in[10];
    const float* b2s = (const float*)d_in[11];
    const float* gammas = (const float*)d_in[12];
    const float* betas = (const float*)d_in[13];
    const float* lin_W = (const float*)d_in[14];
    const float* lin_b = (const float*)d_in[15];
    float* out = (float*)d_out;

    cudaFuncSetAttribute(mlp_gemm_k, cudaFuncAttributeMaxDynamicSharedMemorySize,
                         MLP_SMEM);

    probe_k<<<1, 32>>>((const int*)ei);
    zero_cnt_k<<<(NN + 255) / 256, 256>>>();
    node_embed_k<<<(NN * 32 + 255) / 256, 256>>>(x, node_W, node_b);
    hist_k<<<2048, 256>>>(ei);
    scan_partial_k<<<SCAN_NB, SCAN_B>>>();
    scan_tops_k<<<1, 32>>>();
    scan_final_k<<<SCAN_NB, SCAN_B>>>();
    pos_k<<<(NE + 255) / 256, 256>>>(ei);
    edge_gemm_k<<<NE / 256, 256>>>(ea, edge_W, edge_b);

    // layer buffers: l0: g_h -> g_za ; l1: g_za -> g_zb ; l2: g_zb -> g_za
    int srcsel[NL] = {0, 1, 2};
    int dstsel[NL] = {1, 2, 1};
    for (int l = 0; l < NL; l++) {
        agg_k<<<(NN * 32 + 255) / 256, 256>>>(
            srcsel[l], (l > 0) ? 1 : 0,
            gammas + (l - 1) * 64, betas + (l - 1) * 64);
        mlp_gemm_k<<<(NN + 63) / 64, 256, MLP_SMEM>>>(
            dstsel[l],
            W1s + (size_t)l * 64 * 128, b1s + (size_t)l * 128,
            W2s + (size_t)l * 128 * 64, b2s + (size_t)l * 64);
        bn_finalize_k<<<1, 64>>>();
    }

    pool_final_k<<<NG, 256>>>(1, batch, gammas + 2 * 64, betas + 2 * 64,
                              lin_W, lin_b, out);
}

// round 16
// speedup vs baseline: 1.3184x; 1.3184x over previous
#include <cuda_runtime.h>
#include <cuda_fp16.h>

#define NN 50000
#define NE 1600000
#define NG 64
#define FN 32
#define FE 16
#define HD 64
#define NL 3
#define BN_EPS 1e-5f
#define SCAN_B 1024
#define SCAN_NB ((NN + SCAN_B - 1) / SCAN_B)   // 49

typedef unsigned long long ull;

// ---------------- static device scratch (no allocs allowed) ----------------
__device__ __half g_hfa[(size_t)NN * HD];       // fp16 node features (ping)
__device__ __half g_hfb[(size_t)NN * HD];       // fp16 node features (pong)
__device__ float  g_za[(size_t)NN * HD];        // z2 ping (fp32)
__device__ float  g_zb[(size_t)NN * HD];        // z2 pong (fp32)
__device__ float  g_zt[(size_t)NN * HD];        // agg output z (fp32)
__device__ __half g_e[(size_t)NE * HD];         // edge embeddings (fp16), EDGE order
__device__ int    g_src[NE];                    // src node per CSR slot
__device__ int    g_perm[NE];                   // CSR slot -> edge id
__device__ int    g_rowptr[NN + 1];
__device__ int    g_cnt[NN];                    // histogram, then cursor
__device__ int    g_bsum[SCAN_NB];
__device__ int    g_boff[SCAN_NB];
__device__ float  g_part[128];                  // BN sum/sumsq accumulators
__device__ float  g_mu[HD], g_inv[HD];
__device__ int    g_is64;                       // index dtype flag

// ---- f32x2 packed helpers (Blackwell FFMA2) ----
__device__ __forceinline__ ull pack2(float lo, float hi) {
    ull r;
    asm("mov.b64 %0, {%1, %2};" : "=l"(r) : "f"(lo), "f"(hi));
    return r;
}
__device__ __forceinline__ void unpack2(ull v, float& lo, float& hi) {
    asm("mov.b64 {%0, %1}, %2;" : "=f"(lo), "=f"(hi) : "l"(v));
}
__device__ __forceinline__ void fma2(ull& d, ull a, ull b) {
    asm("fma.rn.f32x2 %0, %1, %2, %0;" : "+l"(d) : "l"(a), "l"(b));
}

__device__ __forceinline__ int load_idx(const void* p, long long i, int is64) {
    if (is64) return (int)((const long long*)p)[i];
    return ((const int*)p)[i];
}

__device__ __forceinline__ const float* zbuf_sel(int s) {
    return (s == 1) ? g_za : g_zb;
}
__device__ __forceinline__ float* zbuf_sel_w(int s) {
    return (s == 1) ? g_za : g_zb;
}

// Detect whether ei is int64 (all odd int32 slots == 0) or int32.
__global__ void probe_k(const int* __restrict__ ei32) {
    if (threadIdx.x != 0 || blockIdx.x != 0) return;
    int all0 = 1;
    for (int k = 0; k < 256; k++) {
        long long slot = 1 + 2LL * ((long long)k * 6247);
        if (slot < 2LL * NE && ei32[slot] != 0) { all0 = 0; break; }
    }
    g_is64 = all0;
}

__global__ void zero_cnt_k() {
    int i = blockIdx.x * blockDim.x + threadIdx.x;
    if (i < NN) g_cnt[i] = 0;
}

// h = x @ node_W + node_b   (warp per row, lane owns 2 cols) -> fp16
__global__ void node_embed_k(const float* __restrict__ x,
                             const float* __restrict__ W,
                             const float* __restrict__ b) {
    int r = (blockIdx.x * blockDim.x + threadIdx.x) >> 5;
    int lane = threadIdx.x & 31;
    if (r >= NN) return;
    float2 acc = make_float2(b[2 * lane], b[2 * lane + 1]);
    const float* xr = x + (size_t)r * FN;
#pragma unroll
    for (int k = 0; k < FN; k++) {
        float xv = __ldg(xr + k);
        float2 wv = *(const float2*)(W + k * HD + 2 * lane);
        acc.x += xv * wv.x;
        acc.y += xv * wv.y;
    }
    ((__half2*)g_hfa)[(size_t)r * 32 + lane] = __float22half2_rn(acc);
}

__global__ void hist_k(const void* __restrict__ ei) {
    int is64 = g_is64;
    for (long long i = blockIdx.x * blockDim.x + threadIdx.x; i < NE;
         i += (long long)gridDim.x * blockDim.x)
        atomicAdd(&g_cnt[load_idx(ei, NE + i, is64)], 1);
}

// ---- 3-kernel coalesced exclusive scan of g_cnt -> g_rowptr (+cursor) ----
__global__ void scan_partial_k() {
    int i = blockIdx.x * SCAN_B + threadIdx.x;
    int v = (i < NN) ? g_cnt[i] : 0;
    int lane = threadIdx.x & 31, w = threadIdx.x >> 5;
#pragma unroll
    for (int off = 16; off; off >>= 1) v += __shfl_down_sync(0xffffffffu, v, off);
    __shared__ int ws[32];
    if (lane == 0) ws[w] = v;
    __syncthreads();
    if (w == 0) {
        int t = ws[lane];
#pragma unroll
        for (int off = 16; off; off >>= 1) t += __shfl_down_sync(0xffffffffu, t, off);
        if (lane == 0) g_bsum[blockIdx.x] = t;
    }
}

__global__ void scan_tops_k() {
    if (threadIdx.x != 0) return;
    int run = 0;
    for (int b = 0; b < SCAN_NB; b++) {
        g_boff[b] = run;
        run += g_bsum[b];
    }
    g_rowptr[NN] = run;
}

__global__ void scan_final_k() {
    int i = blockIdx.x * SCAN_B + threadIdx.x;
    int v = (i < NN) ? g_cnt[i] : 0;
    int lane = threadIdx.x & 31, w = threadIdx.x >> 5;
    int inc = v;
#pragma unroll
    for (int off = 1; off < 32; off <<= 1) {
        int n = __shfl_up_sync(0xffffffffu, inc, off);
        if (lane >= off) inc += n;
    }
    __shared__ int ws[32];
    if (lane == 31) ws[w] = inc;
    __syncthreads();
    if (w == 0) {
        int t = ws[lane];
        int e = t;
#pragma unroll
        for (int off = 1; off < 32; off <<= 1) {
            int n = __shfl_up_sync(0xffffffffu, e, off);
            if (lane >= off) e += n;
        }
        ws[lane] = e - t;  // exclusive warp offset
    }
    __syncthreads();
    int excl = g_boff[blockIdx.x] + ws[w] + inc - v;
    if (i < NN) { g_rowptr[i] = excl; g_cnt[i] = excl; }
}

// thread per edge: assign CSR slot, record src + perm
__global__ void pos_k(const void* __restrict__ ei) {
    long long i = (long long)blockIdx.x * blockDim.x + threadIdx.x;
    if (i >= NE) return;
    int is64 = g_is64;
    int dst = load_idx(ei, NE + i, is64);
    int p = atomicAdd(&g_cnt[dst], 1);
    g_src[p] = load_idx(ei, i, is64);
    g_perm[p] = (int)i;
}

// e = edge_attr @ edge_W + edge_b (fp16), EDGE order, coalesced writes.
// Tiled GEMM: 256 edges/block, thread = 8 edges x 8 cols, f32x2 FMA.
__global__ __launch_bounds__(256) void edge_gemm_k(const float* __restrict__ ea,
                                                   const float* __restrict__ W,
                                                   const float* __restrict__ b) {
    __shared__ __align__(16) float sea[256 * 17];
    __shared__ __align__(16) float sW[16 * 64];
    __shared__ __align__(16) float sb[64];
    int tid = threadIdx.x;
    long long e0 = (long long)blockIdx.x * 256;
    const float4* gea = (const float4*)(ea + e0 * FE);
    for (int i = tid; i < 1024; i += 256) {
        float4 v = gea[i];
        int e = i >> 2, k4 = (i & 3) << 2;
        float* d = &sea[e * 17 + k4];
        d[0] = v.x; d[1] = v.y; d[2] = v.z; d[3] = v.w;
    }
    for (int i = tid; i < 1024; i += 256) sW[i] = W[i];
    if (tid < 64) sb[tid] = b[tid];
    __syncthreads();

    int cg = tid & 7, eg = tid >> 3;     // 8 col-groups x 32 edge-groups
    ull acc[8][4];
#pragma unroll
    for (int p = 0; p < 4; p++) {
        ull bv = *(const ull*)&sb[cg * 8 + 2 * p];
#pragma unroll
        for (int j = 0; j < 8; j++) acc[j][p] = bv;
    }
#pragma unroll
    for (int k = 0; k < FE; k++) {
        ull w0 = *(const ull*)&sW[k * 64 + cg * 8];
        ull w1 = *(const ull*)&sW[k * 64 + cg * 8 + 2];
        ull w2 = *(const ull*)&sW[k * 64 + cg * 8 + 4];
        ull w3 = *(const ull*)&sW[k * 64 + cg * 8 + 6];
#pragma unroll
        for (int j = 0; j < 8; j++) {
            float a = sea[(eg * 8 + j) * 17 + k];
            ull a2 = pack2(a, a);
            fma2(acc[j][0], a2, w0);
            fma2(acc[j][1], a2, w1);
            fma2(acc[j][2], a2, w2);
            fma2(acc[j][3], a2, w3);
        }
    }
#pragma unroll
    for (int j = 0; j < 8; j++) {
        long long e = e0 + eg * 8 + j;
        uint4 o;
        float lo, hi;
        __half2 hh;
        unpack2(acc[j][0], lo, hi); hh = __floats2half2_rn(lo, hi); o.x = *(unsigned*)&hh;
        unpack2(acc[j][1], lo, hi); hh = __floats2half2_rn(lo, hi); o.y = *(unsigned*)&hh;
        unpack2(acc[j][2], lo, hi); hh = __floats2half2_rn(lo, hi); o.z = *(unsigned*)&hh;
        unpack2(acc[j][3], lo, hi); hh = __floats2half2_rn(lo, hi); o.w = *(unsigned*)&hh;
        *(uint4*)(g_e + (size_t)e * HD + cg * 8) = o;
    }
}

// warp per dst node: z = h + sum_in relu(h[src] + e)   (h already BN'd, fp16)
__global__ void agg_k(int use_a) {
    int v = (blockIdx.x * blockDim.x + threadIdx.x) >> 5;
    int lane = threadIdx.x & 31;
    if (v >= NN) return;
    const __half2* hp = (const __half2*)(use_a ? g_hfa : g_hfb);
    const __half2* ep = (const __half2*)g_e;
    const __half2 zz = __float2half2_rn(0.f);

    int s0 = g_rowptr[v], s1 = g_rowptr[v + 1];
    float2 acc = make_float2(0.f, 0.f);
    for (int s = s0; s < s1; s += 32) {
        int n = min(32, s1 - s);
        int mysrc = 0, myperm = 0;
        if (lane < n) {
            mysrc = __ldg(&g_src[s + lane]);
            myperm = __ldg(&g_perm[s + lane]);
        }
        if (n == 32) {
#pragma unroll 8
            for (int j = 0; j < 32; j++) {
                int sc = __shfl_sync(0xffffffffu, mysrc, j);
                int pe = __shfl_sync(0xffffffffu, myperm, j);
                __half2 ev = ep[(size_t)pe * 32 + lane];
                __half2 hs = hp[(size_t)sc * 32 + lane];
                float2 m = __half22float2(__hmax2(__hadd2(hs, ev), zz));
                acc.x += m.x;
                acc.y += m.y;
            }
        } else {
            for (int j = 0; j < n; j++) {
                int sc = __shfl_sync(0xffffffffu, mysrc, j);
                int pe = __shfl_sync(0xffffffffu, myperm, j);
                __half2 ev = ep[(size_t)pe * 32 + lane];
                __half2 hs = hp[(size_t)sc * 32 + lane];
                float2 m = __half22float2(__hmax2(__hadd2(hs, ev), zz));
                acc.x += m.x;
                acc.y += m.y;
            }
        }
    }
    float2 hv = __half22float2(hp[(size_t)v * 32 + lane]);
    *(float2*)(g_zt + (size_t)v * HD + 2 * lane) =
        make_float2(hv.x + acc.x, hv.y + acc.y);
}

// GINE MLP as register-tiled GEMM pair + fused BN-stat accumulation.
#define SZ_OFF   0
#define SW_OFF   4352                 // 64*68
#define SH_OFF   (SW_OFF + 8192)      // + 64*128
#define SB1_OFF  (SH_OFF + 8448)      // + 64*132
#define SB2_OFF  (SB1_OFF + 128)
#define MLP_SMEM ((SB2_OFF + 64) * 4)
__global__ __launch_bounds__(256) void mlp_gemm_k(int dstsel,
                                                  const float* __restrict__ W1,
                                                  const float* __restrict__ b1,
                                                  const float* __restrict__ W2,
                                                  const float* __restrict__ b2) {
    extern __shared__ __align__(16) float sm[];
    float* sz = sm + SZ_OFF;    // [64][68]
    float* sW = sm + SW_OFF;    // [64][128] then [128][64]
    float* sh = sm + SH_OFF;    // [64][132]
    float* sb1 = sm + SB1_OFF;
    float* sb2 = sm + SB2_OFF;
    __shared__ float sstat[128];
    int tid = threadIdx.x;
    int r0 = blockIdx.x * 64;

    if (tid < 128) sstat[tid] = 0.f;
    for (int i = tid; i < 1024; i += 256) {
        int r = i >> 4, c4 = (i & 15) << 2;
        float4 v = make_float4(0.f, 0.f, 0.f, 0.f);
        if (r0 + r < NN) v = *(const float4*)&g_zt[(size_t)(r0 + r) * HD + c4];
        *(float4*)&sz[r * 68 + c4] = v;
    }
    for (int i = tid; i < 8192; i += 256) sW[i] = W1[i];
    if (tid < 128) sb1[tid] = b1[tid];
    else if (tid < 192) sb2[tid - 128] = b2[tid - 128];
    __syncthreads();

    // GEMM1: 64x128 = (rg:8 rows x 8) x (cg:32 cols x 4)
    {
        int cg = tid & 31, rg = tid >> 5;
        ull acc[8][2];
        ull bb0 = *(const ull*)&sb1[cg * 4];
        ull bb1 = *(const ull*)&sb1[cg * 4 + 2];
#pragma unroll
        for (int j = 0; j < 8; j++) { acc[j][0] = bb0; acc[j][1] = bb1; }
#pragma unroll 4
        for (int k = 0; k < 64; k++) {
            ull w0 = *(const ull*)&sW[k * 128 + cg * 4];
            ull w1 = *(const ull*)&sW[k * 128 + cg * 4 + 2];
#pragma unroll
            for (int j = 0; j < 8; j++) {
                float a = sz[(rg * 8 + j) * 68 + k];
                ull a2 = pack2(a, a);
                fma2(acc[j][0], a2, w0);
                fma2(acc[j][1], a2, w1);
            }
        }
#pragma unroll
        for (int j = 0; j < 8; j++) {
            float x0, x1, x2, x3;
            unpack2(acc[j][0], x0, x1);
            unpack2(acc[j][1], x2, x3);
            float4 hv = make_float4(fmaxf(x0, 0.f), fmaxf(x1, 0.f),
                                    fmaxf(x2, 0.f), fmaxf(x3, 0.f));
            *(float4*)&sh[(rg * 8 + j) * 132 + cg * 4] = hv;
        }
    }
    __syncthreads();
    for (int i = tid; i < 8192; i += 256) sW[i] = W2[i];
    __syncthreads();

    // GEMM2: 64x64 = (rg2:16 rows x 4) x (cg2:16 cols x 4)
    {
        int cg2 = tid & 15, rg2 = tid >> 4;
        ull acc[4][2];
        ull bb0 = *(const ull*)&sb2[cg2 * 4];
        ull bb1 = *(const ull*)&sb2[cg2 * 4 + 2];
#pragma unroll
        for (int j = 0; j < 4; j++) { acc[j][0] = bb0; acc[j][1] = bb1; }
#pragma unroll 4
        for (int k = 0; k < 128; k++) {
            ull w0 = *(const ull*)&sW[k * 64 + cg2 * 4];
            ull w1 = *(const ull*)&sW[k * 64 + cg2 * 4 + 2];
#pragma unroll
            for (int j = 0; j < 4; j++) {
                float a = sh[(rg2 * 4 + j) * 132 + k];
                ull a2 = pack2(a, a);
                fma2(acc[j][0], a2, w0);
                fma2(acc[j][1], a2, w1);
            }
        }
        float* dstb = zbuf_sel_w(dstsel);
        float cs[4] = {0.f, 0.f, 0.f, 0.f};
        float cq[4] = {0.f, 0.f, 0.f, 0.f};
#pragma unroll
        for (int j = 0; j < 4; j++) {
            int r = r0 + rg2 * 4 + j;
            if (r < NN) {
                float x0, x1, x2, x3;
                unpack2(acc[j][0], x0, x1);
                unpack2(acc[j][1], x2, x3);
                *(float4*)&dstb[(size_t)r * HD + cg2 * 4] =
                    make_float4(x0, x1, x2, x3);
                cs[0] += x0; cs[1] += x1; cs[2] += x2; cs[3] += x3;
                cq[0] += x0 * x0; cq[1] += x1 * x1;
                cq[2] += x2 * x2; cq[3] += x3 * x3;
            }
        }
#pragma unroll
        for (int p = 0; p < 4; p++) {
            atomicAdd(&sstat[cg2 * 4 + p], cs[p]);
            atomicAdd(&sstat[64 + cg2 * 4 + p], cq[p]);
        }
    }
    __syncthreads();
    if (tid < 128) atomicAdd(&g_part[tid], sstat[tid]);
}

// Read BN accumulators, compute mu/inv, RE-ZERO g_part for next use
// (keeps the captured graph deterministic across replays).
__global__ void bn_finalize_k() {
    int t = threadIdx.x;  // 64 threads
    float s = g_part[t];
    float s2 = g_part[64 + t];
    g_part[t] = 0.f;
    g_part[64 + t] = 0.f;
    float mu = s / (float)NN;
    float var = s2 / (float)NN - mu * mu;
    g_mu[t] = mu;
    g_inv[t] = rsqrtf(var + BN_EPS);
}

// Apply BN+relu to z2 (fp32) -> fp16 h buffer (thread owns 2 cols).
__global__ void bn_apply_half_k(int sel, int dsta,
                                const float* __restrict__ gamma,
                                const float* __restrict__ beta) {
    int i = blockIdx.x * blockDim.x + threadIdx.x;
    if (i >= NN * 32) return;
    int r = i >> 5, c2 = i & 31;
    const float* buf = zbuf_sel(sel);
    float a0 = gamma[2 * c2] * g_inv[2 * c2];
    float a1 = gamma[2 * c2 + 1] * g_inv[2 * c2 + 1];
    float b0 = beta[2 * c2] - g_mu[2 * c2] * a0;
    float b1 = beta[2 * c2 + 1] - g_mu[2 * c2 + 1] * a1;
    float2 z = *(const float2*)&buf[(size_t)r * HD + 2 * c2];
    float2 hv = make_float2(fmaxf(fmaf(a0, z.x, b0), 0.f),
                            fmaxf(fmaf(a1, z.y, b1), 0.f));
    __half2* dst = (__half2*)(dsta ? g_hfa : g_hfb);
    dst[(size_t)r * 32 + c2] = __float22half2_rn(hv);
}

// batch sorted -> contiguous ranges; BN+relu on the fly, mean-pool, head.
__global__ void pool_final_k(int sel, const void* __restrict__ batch,
                             const float* __restrict__ gamma,
                             const float* __restrict__ beta,
                             const float* __restrict__ lw,
                             const float* __restrict__ lb,
                             float* __restrict__ out) {
    int g = blockIdx.x;
    int is64 = g_is64;
    const float* buf = zbuf_sel(sel);
    __shared__ int s_range[2];
    if (threadIdx.x == 0) {
        int lo = 0, hi = NN;
        while (lo < hi) { int mid = (lo + hi) >> 1; if (load_idx(batch, mid, is64) < g) lo = mid + 1; else hi = mid; }
        s_range[0] = lo;
        hi = NN;
        while (lo < hi) { int mid = (lo + hi) >> 1; if (load_idx(batch, mid, is64) < g + 1) lo = mid + 1; else hi = mid; }
        s_range[1] = lo;
    }
    __syncthreads();
    int start = s_range[0], end = s_range[1];
    int c = threadIdx.x & 63, rg = threadIdx.x >> 6;
    float a = gamma[c] * g_inv[c];
    float bb = beta[c] - g_mu[c] * a;
    float s = 0.f;
    for (int r = start + rg; r < end; r += 4)
        s += fmaxf(fmaf(a, buf[(size_t)r * HD + c], bb), 0.f);
    __shared__ float ps[256];
    ps[threadIdx.x] = s;
    __syncthreads();
    if (threadIdx.x < 128) ps[threadIdx.x] += ps[threadIdx.x + 128];
    __syncthreads();
    if (threadIdx.x < 64) {
        float gs = ps[threadIdx.x] + ps[threadIdx.x + 64];
        float cnt = fmaxf((float)(end - start), 1.0f);
        ps[threadIdx.x] = gs / cnt * lw[threadIdx.x];
    }
    __syncthreads();
    if (threadIdx.x < 32) {
        float t = ps[threadIdx.x] + ps[threadIdx.x + 32];
#pragma unroll
        for (int off = 16; off; off >>= 1) t += __shfl_down_sync(0xffffffffu, t, off);
        if (threadIdx.x == 0) out[g] = t + lb[0];
    }
}

// ---------------- launcher ----------------
extern "C" void kernel_launch(void* const* d_in, const int* in_sizes, int n_in,
                              void* d_out, int out_size) {
    const float* x = (const float*)d_in[0];
    const float* ea = (const float*)d_in[1];
    const void* ei = d_in[2];
    const void* batch = d_in[3];
    const float* node_W = (const float*)d_in[4];
    const float* node_b = (const float*)d_in[5];
    const float* edge_W = (const float*)d_in[6];
    const float* edge_b = (const float*)d_in[7];
    const float* W1s = (const float*)d_in[8];
    const float* b1s = (const float*)d_in[9];
    const float* W2s = (const float*)d_in[10];
    const float* b2s = (const float*)d_in[11];
    const float* gammas = (const float*)d_in[12];
    const float* betas = (const float*)d_in[13];
    const float* lin_W = (const float*)d_in[14];
    const float* lin_b = (const float*)d_in[15];
    float* out = (float*)d_out;

    cudaFuncSetAttribute(mlp_gemm_k, cudaFuncAttributeMaxDynamicSharedMemorySize,
                         MLP_SMEM);

    probe_k<<<1, 32>>>((const int*)ei);
    zero_cnt_k<<<(NN + 255) / 256, 256>>>();
    node_embed_k<<<(NN * 32 + 255) / 256, 256>>>(x, node_W, node_b);
    hist_k<<<2048, 256>>>(ei);
    scan_partial_k<<<SCAN_NB, SCAN_B>>>();
    scan_tops_k<<<1, 32>>>();
    scan_final_k<<<SCAN_NB, SCAN_B>>>();
    pos_k<<<(NE + 255) / 256, 256>>>(ei);
    edge_gemm_k<<<NE / 256, 256>>>(ea, edge_W, edge_b);

    // l0: hfa -> za ; bn_apply -> hfb
    // l1: hfb -> zb ; bn_apply -> hfa
    // l2: hfa -> za ; pool from za with BN2
    int usea[NL] = {1, 0, 1};
    int dstsel[NL] = {1, 2, 1};
    for (int l = 0; l < NL; l++) {
        agg_k<<<(NN * 32 + 255) / 256, 256>>>(usea[l]);
        mlp_gemm_k<<<(NN + 63) / 64, 256, MLP_SMEM>>>(
            dstsel[l],
            W1s + (size_t)l * 64 * 128, b1s + (size_t)l * 128,
            W2s + (size_t)l * 128 * 64, b2s + (size_t)l * 64);
        bn_finalize_k<<<1, 64>>>();
        if (l < NL - 1) {
            bn_apply_half_k<<<(NN * 32 + 255) / 256, 256>>>(
                dstsel[l], (l == 0) ? 0 : 1, gammas + l * 64, betas + l * 64);
        }
    }

    pool_final_k<<<NG, 256>>>(1, batch, gammas + 2 * 64, betas + 2 * 64,
                              lin_W, lin_b, out);
}